// round 10
// baseline (speedup 1.0000x reference)
#include <cuda_runtime.h>

#define NN      10000
#define EE      320000
#define IND     32
#define HID     64
#define SEQL    168
#define OUTD    10000
#define COMB    (NN*HID + HID)      // 640064
#define COMB4   (COMB/4)            // 160016
#define RPB     16                  // of1 rows per block
#define CH      37                  // of1 comb chunks (37*8 = 296 = 2 blocks/SM, one wave)
#define CAP     128                 // bucket capacity (max degree ~60)

// ---------------- device scratch ----------------
__device__ __align__(16) int   g_head[NN];          // in-degree / fill cursor
__device__ __align__(16) int   g_srcidx[NN * CAP];  // bucketed adjacency
__device__ __align__(16) float g_dinv[NN];
__device__ __align__(16) float g_g[NN * HID];       // h1 = x@W1^T (raw)
__device__ __align__(16) float g_a[NN * HID];       // dinv[n]*h2[n]  (prescaled)
__device__ __align__(16) float g_comb[COMB];
__device__ __align__(16) float g_yp[CH * 128];      // of1 partials [chunk][row]

// ---------------- lin1 (+ head zeroing in trailing blocks) ----------------
// h1[n,f] = sum_k x[n,k] W1[f,k] (raw). Weight LDS reused across 4 nodes.
__global__ void k_lin1z(const float* __restrict__ x, const float* __restrict__ W) {
    if (blockIdx.x >= 313) {                    // trailing 40 blocks: zero g_head
        int i = (blockIdx.x - 313) * 256 + threadIdx.x;
        if (i < NN) g_head[i] = 0;
        return;
    }
    __shared__ float sWf[IND * HID];    // [k][f]
    __shared__ float sx[32][IND];
    int tid = threadIdx.x;
    for (int i = tid; i < HID * IND; i += 256) {
        int f = i >> 5, k = i & 31;
        sWf[k * HID + f] = W[i];
    }
    int node0 = blockIdx.x * 32;
    for (int i = tid; i < 32 * IND; i += 256) {
        int ln = i >> 5, k = i & 31;
        int n = node0 + ln;
        sx[ln][k] = (n < NN) ? x[n * IND + k] : 0.f;
    }
    __syncthreads();
    int fp = tid & 31;
    int grp = tid >> 5;
    const float2* sW2 = (const float2*)sWf;
    float2 a0 = make_float2(0.f, 0.f), a1 = a0, a2 = a0, a3 = a0;
    #pragma unroll
    for (int k = 0; k < IND; k++) {
        float2 w = sW2[k * 32 + fp];
        float x0 = sx[grp * 4 + 0][k];
        float x1 = sx[grp * 4 + 1][k];
        float x2 = sx[grp * 4 + 2][k];
        float x3 = sx[grp * 4 + 3][k];
        a0.x = fmaf(w.x, x0, a0.x); a0.y = fmaf(w.y, x0, a0.y);
        a1.x = fmaf(w.x, x1, a1.x); a1.y = fmaf(w.y, x1, a1.y);
        a2.x = fmaf(w.x, x2, a2.x); a2.y = fmaf(w.y, x2, a2.y);
        a3.x = fmaf(w.x, x3, a3.x); a3.y = fmaf(w.y, x3, a3.y);
    }
    float2* gp = (float2*)g_g;
    int nb = node0 + grp * 4;
    if (nb + 0 < NN) gp[(nb + 0) * 32 + fp] = a0;
    if (nb + 1 < NN) gp[(nb + 1) * 32 + fp] = a1;
    if (nb + 2 < NN) gp[(nb + 2) * 32 + fp] = a2;
    if (nb + 3 < NN) gp[(nb + 3) * 32 + fp] = a3;
}

// ---------------- bucket fill ----------------
__global__ void k_fill(const int* __restrict__ ei) {
    int i = blockIdx.x * blockDim.x + threadIdx.x;
    if (i < EE / 4) {
        int4 s4 = ((const int4*)ei)[i];
        int4 d4 = ((const int4*)(ei + EE))[i];
        int p;
        if ((unsigned)d4.x < NN) { p = atomicAdd(&g_head[d4.x], 1); if (p < CAP) g_srcidx[d4.x * CAP + p] = s4.x; }
        if ((unsigned)d4.y < NN) { p = atomicAdd(&g_head[d4.y], 1); if (p < CAP) g_srcidx[d4.y * CAP + p] = s4.y; }
        if ((unsigned)d4.z < NN) { p = atomicAdd(&g_head[d4.z], 1); if (p < CAP) g_srcidx[d4.z * CAP + p] = s4.z; }
        if ((unsigned)d4.w < NN) { p = atomicAdd(&g_head[d4.w], 1); if (p < CAP) g_srcidx[d4.w * CAP + p] = s4.w; }
    }
}

// ---------------- dinv + weather MLP ----------------
__global__ void k_dinvW(const float* __restrict__ rain, const float* __restrict__ frain,
                        const float* __restrict__ w1W, const float* __restrict__ w1b,
                        const float* __restrict__ w2W, const float* __restrict__ w2b) {
    int b = blockIdx.x, tid = threadIdx.x;
    if (b < 40) {
        int i = b * 256 + tid;
        if (i < NN) g_dinv[i] = rsqrtf((float)(g_head[i] + 1));
        return;
    }
    __shared__ float w[HID];
    if (tid < HID) {
        float s = w1b[tid];
        const float* row = w1W + tid * (SEQL + 1);
        #pragma unroll 4
        for (int k = 0; k < SEQL; k++) s = fmaf(row[k], rain[k], s);
        s = fmaf(row[SEQL], frain[0], s);
        w[tid] = fmaxf(s, 0.f);
    }
    __syncthreads();
    if (tid < HID) {
        float t = w2b[tid];
        const float* r2 = w2W + tid * HID;
        #pragma unroll 8
        for (int k = 0; k < HID; k++) t = fmaf(r2[k], w[k], t);
        g_comb[NN * HID + tid] = t;
    }
}

// ---------------- gather (weighted, layer1): acc = dinv[n]*h[n] + sum_s dinv[s]*h[s] ----------------
__device__ __forceinline__ float2 gather_w(const float2* __restrict__ gp, int node, int lane) {
    float di = g_dinv[node];
    float2 self = gp[node * 32 + lane];
    float2 acc = make_float2(di * self.x, di * self.y);
    int deg = g_head[node]; if (deg > CAP) deg = CAP;
    const int* __restrict__ bk = g_srcidx + node * CAP;
    int e = 0;
    for (; e + 4 <= deg; e += 4) {
        int4 s4 = *(const int4*)(bk + e);          // 16B-aligned (CAP=128)
        float d0 = g_dinv[s4.x], d1 = g_dinv[s4.y], d2 = g_dinv[s4.z], d3 = g_dinv[s4.w];
        float2 v0 = gp[s4.x * 32 + lane];
        float2 v1 = gp[s4.y * 32 + lane];
        float2 v2 = gp[s4.z * 32 + lane];
        float2 v3 = gp[s4.w * 32 + lane];
        acc.x = fmaf(d0, v0.x, acc.x); acc.y = fmaf(d0, v0.y, acc.y);
        acc.x = fmaf(d1, v1.x, acc.x); acc.y = fmaf(d1, v1.y, acc.y);
        acc.x = fmaf(d2, v2.x, acc.x); acc.y = fmaf(d2, v2.y, acc.y);
        acc.x = fmaf(d3, v3.x, acc.x); acc.y = fmaf(d3, v3.y, acc.y);
    }
    for (; e < deg; e++) {
        int s = bk[e];
        float ds = g_dinv[s];
        float2 v = gp[s * 32 + lane];
        acc.x = fmaf(ds, v.x, acc.x); acc.y = fmaf(ds, v.y, acc.y);
    }
    return acc;
}

// ---------------- gather (pure sum, layer2 over prescaled g_a) ----------------
__device__ __forceinline__ float2 gather_s(const float2* __restrict__ gp, int node, int lane) {
    float2 acc = gp[node * 32 + lane];             // self term already dinv-scaled
    int deg = g_head[node]; if (deg > CAP) deg = CAP;
    const int* __restrict__ bk = g_srcidx + node * CAP;
    int e = 0;
    for (; e + 4 <= deg; e += 4) {
        int4 s4 = *(const int4*)(bk + e);
        float2 v0 = gp[s4.x * 32 + lane];
        float2 v1 = gp[s4.y * 32 + lane];
        float2 v2 = gp[s4.z * 32 + lane];
        float2 v3 = gp[s4.w * 32 + lane];
        acc.x += (v0.x + v1.x) + (v2.x + v3.x);
        acc.y += (v0.y + v1.y) + (v2.y + v3.y);
    }
    for (; e < deg; e++) {
        int s = bk[e];
        float2 v = gp[s * 32 + lane];
        acc.x += v.x; acc.y += v.y;
    }
    return acc;
}

// ---------------- fused agg1 + lin2: 4 nodes/warp; stores dinv[n]*h2 ----------------
__global__ void k_aggLin(const float* __restrict__ b1, const float* __restrict__ W2) {
    __shared__ float sW2t[HID * HID];   // [k][f]
    __shared__ float sa1[8][HID];
    int tid = threadIdx.x, lane = tid & 31, wid = tid >> 5;
    for (int i = tid; i < HID * HID; i += 256) {
        int f = i >> 6, k = i & 63;
        sW2t[k * HID + f] = W2[i];
    }
    __syncthreads();
    int f = lane * 2;
    float bx = b1[f], by = b1[f + 1];
    const float2* sW2v = (const float2*)sW2t;
    #pragma unroll
    for (int rep = 0; rep < 4; rep++) {
        int node = blockIdx.x * 32 + wid * 4 + rep;
        if (node >= NN) continue;
        float2 acc = gather_w((const float2*)g_g, node, lane);
        float dn = g_dinv[node];
        sa1[wid][f]     = fmaxf(fmaf(dn, acc.x, bx), 0.f);
        sa1[wid][f + 1] = fmaxf(fmaf(dn, acc.y, by), 0.f);
        __syncwarp();
        float h0 = 0.f, h1v = 0.f;
        #pragma unroll 8
        for (int k = 0; k < HID; k++) {
            float a = sa1[wid][k];
            float2 w = sW2v[k * 32 + lane];
            h0  = fmaf(a, w.x, h0);
            h1v = fmaf(a, w.y, h1v);
        }
        ((float2*)g_a)[node * 32 + lane] = make_float2(dn * h0, dn * h1v);
        __syncwarp();
    }
}

// ---------------- agg2: pure-sum gather, clip [0,10], write comb ----------------
__global__ void k_agg2(const float* __restrict__ b2) {
    int tid = threadIdx.x, lane = tid & 31, wid = tid >> 5;
    int node = blockIdx.x * 8 + wid;
    if (node >= NN) return;
    float2 acc = gather_s((const float2*)g_a, node, lane);
    float dn = g_dinv[node];
    int f = lane * 2;
    float ox = fminf(fmaxf(fmaf(dn, acc.x, b2[f]),     0.f), 10.f);
    float oy = fminf(fmaxf(fmaf(dn, acc.y, b2[f + 1]), 0.f), 10.f);
    ((float2*)g_comb)[node * 32 + lane] = make_float2(ox, oy);
}

// ---------------- of1 matvec: race-free partials, no atomics ----------------
__global__ void k_of1(const float* __restrict__ W) {
    int r0 = blockIdx.y * RPB;
    const float4* __restrict__ v4 = (const float4*)g_comb;
    const float4* __restrict__ W4 = (const float4*)W;
    float acc[RPB];
    #pragma unroll
    for (int r = 0; r < RPB; r++) acc[r] = 0.f;
    int stride = gridDim.x * blockDim.x;
    for (int i = blockIdx.x * blockDim.x + threadIdx.x; i < COMB4; i += stride) {
        float4 c = v4[i];
        #pragma unroll
        for (int r = 0; r < RPB; r++) {
            float4 a = __ldcs(&W4[(size_t)(r0 + r) * COMB4 + i]);
            acc[r] = fmaf(a.x, c.x, acc[r]);
            acc[r] = fmaf(a.y, c.y, acc[r]);
            acc[r] = fmaf(a.z, c.z, acc[r]);
            acc[r] = fmaf(a.w, c.w, acc[r]);
        }
    }
    int lane = threadIdx.x & 31, wid = threadIdx.x >> 5;
    #pragma unroll
    for (int r = 0; r < RPB; r++) {
        #pragma unroll
        for (int o = 16; o > 0; o >>= 1)
            acc[r] += __shfl_down_sync(0xffffffffu, acc[r], o);
    }
    __shared__ float red[8][RPB];
    if (lane == 0) {
        #pragma unroll
        for (int r = 0; r < RPB; r++) red[wid][r] = acc[r];
    }
    __syncthreads();
    if (threadIdx.x < RPB) {
        float s = 0.f;
        #pragma unroll
        for (int w = 0; w < 8; w++) s += red[w][threadIdx.x];
        g_yp[blockIdx.x * 128 + r0 + threadIdx.x] = s;   // partial per chunk
    }
}

// ---------------- of2: reduce partials + final projection ----------------
__global__ void k_of2(const float* __restrict__ of1b, const float* __restrict__ of2W,
                      const float* __restrict__ of2b, float* __restrict__ out) {
    __shared__ float so[128];
    int tid = threadIdx.x;
    if (tid < 128) {
        float s = of1b[tid];
        #pragma unroll
        for (int c = 0; c < CH; c++) s += g_yp[c * 128 + tid];
        so[tid] = fmaxf(s, 0.f);
    }
    __syncthreads();
    int k = blockIdx.x * blockDim.x + tid;
    if (k < OUTD) {
        const float4* __restrict__ w4 = (const float4*)(of2W + (size_t)k * 128);
        float s = of2b[k];
        #pragma unroll
        for (int j = 0; j < 32; j++) {
            float4 a = __ldg(&w4[j]);
            s = fmaf(a.x, so[j * 4 + 0], s);
            s = fmaf(a.y, so[j * 4 + 1], s);
            s = fmaf(a.z, so[j * 4 + 2], s);
            s = fmaf(a.w, so[j * 4 + 3], s);
        }
        out[k] = s;
    }
}

// ---------------- host ----------------
extern "C" void kernel_launch(void* const* d_in, const int* in_sizes, int n_in,
                              void* d_out, int out_size) {
    const float* x     = (const float*)d_in[0];
    const int*   ei    = (const int*)d_in[1];
    const float* rain  = (const float*)d_in[2];
    const float* frain = (const float*)d_in[3];
    const float* W1    = (const float*)d_in[4];
    const float* b1    = (const float*)d_in[5];
    const float* W2    = (const float*)d_in[6];
    const float* b2    = (const float*)d_in[7];
    const float* wf1W  = (const float*)d_in[8];
    const float* wf1b  = (const float*)d_in[9];
    const float* wf2W  = (const float*)d_in[10];
    const float* wf2b  = (const float*)d_in[11];
    const float* of1W  = (const float*)d_in[12];
    const float* of1b  = (const float*)d_in[13];
    const float* of2W  = (const float*)d_in[14];
    const float* of2b  = (const float*)d_in[15];
    float* out = (float*)d_out;

    k_lin1z <<<353, 256>>>(x, W1);                 // h1 + zero heads
    k_fill  <<<(EE / 4 + 255) / 256, 256>>>(ei);   // buckets + degrees
    k_dinvW <<<41, 256>>>(rain, frain, wf1W, wf1b, wf2W, wf2b);
    k_aggLin<<<(NN + 31) / 32, 256>>>(b1, W2);     // agg1 + lin2 (prescaled out)
    k_agg2  <<<(NN + 7) / 8, 256>>>(b2);           // pure-sum gather -> comb
    k_of1   <<<dim3(CH, 8), 256>>>(of1W);          // partials, no atomics
    k_of2   <<<(OUTD + 255) / 256, 256>>>(of1b, of2W, of2b, out);
}

// round 11
// speedup vs baseline: 1.0991x; 1.0991x over previous
#include <cuda_runtime.h>

#define NN      10000
#define EE      320000
#define IND     32
#define HID     64
#define SEQL    168
#define OUTD    10000
#define COMB    (NN*HID + HID)      // 640064
#define COMB4   (COMB/4)            // 160016
#define RPB     16                  // of1 rows per block
#define CH      37                  // of1 comb chunks (37*8 = 296 = 2 blocks/SM, one wave)
#define CAP     128                 // bucket capacity (max degree ~60)

// ---------------- device scratch ----------------
__device__ __align__(16) int   g_head[NN];          // in-degree / fill cursor
__device__ __align__(16) int   g_srcidx[NN * CAP];  // bucketed adjacency
__device__ __align__(16) float g_dinv[NN];
__device__ __align__(16) float g_g[NN * HID];       // h1 = x@W1^T (raw)
__device__ __align__(16) float g_a[NN * HID];       // dinv[n]*h2[n]  (prescaled)
__device__ __align__(16) float g_comb[COMB];
__device__ __align__(16) float g_yp[CH * 128];      // of1 partials [chunk][row]

// ---------------- lin1 (+ head zeroing in trailing blocks) ----------------
__global__ void k_lin1z(const float* __restrict__ x, const float* __restrict__ W) {
    if (blockIdx.x >= 313) {                    // trailing 40 blocks: zero g_head
        int i = (blockIdx.x - 313) * 256 + threadIdx.x;
        if (i < NN) g_head[i] = 0;
        return;
    }
    __shared__ float sWf[IND * HID];    // [k][f]
    __shared__ float sx[32][IND];
    int tid = threadIdx.x;
    for (int i = tid; i < HID * IND; i += 256) {
        int f = i >> 5, k = i & 31;
        sWf[k * HID + f] = W[i];
    }
    int node0 = blockIdx.x * 32;
    for (int i = tid; i < 32 * IND; i += 256) {
        int ln = i >> 5, k = i & 31;
        int n = node0 + ln;
        sx[ln][k] = (n < NN) ? x[n * IND + k] : 0.f;
    }
    __syncthreads();
    int fp = tid & 31;
    int grp = tid >> 5;
    const float2* sW2 = (const float2*)sWf;
    float2 a0 = make_float2(0.f, 0.f), a1 = a0, a2 = a0, a3 = a0;
    #pragma unroll
    for (int k = 0; k < IND; k++) {
        float2 w = sW2[k * 32 + fp];
        float x0 = sx[grp * 4 + 0][k];
        float x1 = sx[grp * 4 + 1][k];
        float x2 = sx[grp * 4 + 2][k];
        float x3 = sx[grp * 4 + 3][k];
        a0.x = fmaf(w.x, x0, a0.x); a0.y = fmaf(w.y, x0, a0.y);
        a1.x = fmaf(w.x, x1, a1.x); a1.y = fmaf(w.y, x1, a1.y);
        a2.x = fmaf(w.x, x2, a2.x); a2.y = fmaf(w.y, x2, a2.y);
        a3.x = fmaf(w.x, x3, a3.x); a3.y = fmaf(w.y, x3, a3.y);
    }
    float2* gp = (float2*)g_g;
    int nb = node0 + grp * 4;
    if (nb + 0 < NN) gp[(nb + 0) * 32 + fp] = a0;
    if (nb + 1 < NN) gp[(nb + 1) * 32 + fp] = a1;
    if (nb + 2 < NN) gp[(nb + 2) * 32 + fp] = a2;
    if (nb + 3 < NN) gp[(nb + 3) * 32 + fp] = a3;
}

// ---------------- bucket fill ----------------
__global__ void k_fill(const int* __restrict__ ei) {
    int i = blockIdx.x * blockDim.x + threadIdx.x;
    if (i < EE / 4) {
        int4 s4 = ((const int4*)ei)[i];
        int4 d4 = ((const int4*)(ei + EE))[i];
        int p;
        if ((unsigned)d4.x < NN) { p = atomicAdd(&g_head[d4.x], 1); if (p < CAP) g_srcidx[d4.x * CAP + p] = s4.x; }
        if ((unsigned)d4.y < NN) { p = atomicAdd(&g_head[d4.y], 1); if (p < CAP) g_srcidx[d4.y * CAP + p] = s4.y; }
        if ((unsigned)d4.z < NN) { p = atomicAdd(&g_head[d4.z], 1); if (p < CAP) g_srcidx[d4.z * CAP + p] = s4.z; }
        if ((unsigned)d4.w < NN) { p = atomicAdd(&g_head[d4.w], 1); if (p < CAP) g_srcidx[d4.w * CAP + p] = s4.w; }
    }
}

// ---------------- dinv + weather MLP ----------------
__global__ void k_dinvW(const float* __restrict__ rain, const float* __restrict__ frain,
                        const float* __restrict__ w1W, const float* __restrict__ w1b,
                        const float* __restrict__ w2W, const float* __restrict__ w2b) {
    int b = blockIdx.x, tid = threadIdx.x;
    if (b < 40) {
        int i = b * 256 + tid;
        if (i < NN) g_dinv[i] = rsqrtf((float)(g_head[i] + 1));
        return;
    }
    __shared__ float w[HID];
    if (tid < HID) {
        float s = w1b[tid];
        const float* row = w1W + tid * (SEQL + 1);
        #pragma unroll 4
        for (int k = 0; k < SEQL; k++) s = fmaf(row[k], rain[k], s);
        s = fmaf(row[SEQL], frain[0], s);
        w[tid] = fmaxf(s, 0.f);
    }
    __syncthreads();
    if (tid < HID) {
        float t = w2b[tid];
        const float* r2 = w2W + tid * HID;
        #pragma unroll 8
        for (int k = 0; k < HID; k++) t = fmaf(r2[k], w[k], t);
        g_comb[NN * HID + tid] = t;
    }
}

// ---------------- gather (weighted, layer1): acc = dinv[n]*h[n] + sum_s dinv[s]*h[s] ----------------
__device__ __forceinline__ float2 gather_w(const float2* __restrict__ gp, int node, int lane) {
    float di = g_dinv[node];
    float2 self = gp[node * 32 + lane];
    float2 acc = make_float2(di * self.x, di * self.y);
    int deg = g_head[node]; if (deg > CAP) deg = CAP;
    const int* __restrict__ bk = g_srcidx + node * CAP;
    int e = 0;
    for (; e + 4 <= deg; e += 4) {
        int4 s4 = *(const int4*)(bk + e);          // 16B-aligned (CAP=128)
        float d0 = g_dinv[s4.x], d1 = g_dinv[s4.y], d2 = g_dinv[s4.z], d3 = g_dinv[s4.w];
        float2 v0 = gp[s4.x * 32 + lane];
        float2 v1 = gp[s4.y * 32 + lane];
        float2 v2 = gp[s4.z * 32 + lane];
        float2 v3 = gp[s4.w * 32 + lane];
        acc.x = fmaf(d0, v0.x, acc.x); acc.y = fmaf(d0, v0.y, acc.y);
        acc.x = fmaf(d1, v1.x, acc.x); acc.y = fmaf(d1, v1.y, acc.y);
        acc.x = fmaf(d2, v2.x, acc.x); acc.y = fmaf(d2, v2.y, acc.y);
        acc.x = fmaf(d3, v3.x, acc.x); acc.y = fmaf(d3, v3.y, acc.y);
    }
    for (; e < deg; e++) {
        int s = bk[e];
        float ds = g_dinv[s];
        float2 v = gp[s * 32 + lane];
        acc.x = fmaf(ds, v.x, acc.x); acc.y = fmaf(ds, v.y, acc.y);
    }
    return acc;
}

// ---------------- gather (pure sum, layer2 over prescaled g_a) ----------------
__device__ __forceinline__ float2 gather_s(const float2* __restrict__ gp, int node, int lane) {
    float2 acc = gp[node * 32 + lane];             // self term already dinv-scaled
    int deg = g_head[node]; if (deg > CAP) deg = CAP;
    const int* __restrict__ bk = g_srcidx + node * CAP;
    int e = 0;
    for (; e + 4 <= deg; e += 4) {
        int4 s4 = *(const int4*)(bk + e);
        float2 v0 = gp[s4.x * 32 + lane];
        float2 v1 = gp[s4.y * 32 + lane];
        float2 v2 = gp[s4.z * 32 + lane];
        float2 v3 = gp[s4.w * 32 + lane];
        acc.x += (v0.x + v1.x) + (v2.x + v3.x);
        acc.y += (v0.y + v1.y) + (v2.y + v3.y);
    }
    for (; e < deg; e++) {
        int s = bk[e];
        float2 v = gp[s * 32 + lane];
        acc.x += v.x; acc.y += v.y;
    }
    return acc;
}

// ---------------- fused agg1 + lin2: 1024 threads, 32 warps, ONE node per warp ----------------
// W2 smem amortized over 32 nodes; no serial rep loop; occ ~50% (was 23%).
__global__ void __launch_bounds__(1024, 1)
k_aggLin(const float* __restrict__ b1, const float* __restrict__ W2) {
    __shared__ float sW2t[HID * HID];   // [k][f]
    __shared__ float sa1[32][HID];
    int tid = threadIdx.x, lane = tid & 31, wid = tid >> 5;
    for (int i = tid; i < HID * HID; i += 1024) {
        int f = i >> 6, k = i & 63;
        sW2t[k * HID + f] = W2[i];
    }
    __syncthreads();
    int node = blockIdx.x * 32 + wid;
    if (node >= NN) return;
    int f = lane * 2;
    float2 acc = gather_w((const float2*)g_g, node, lane);
    float dn = g_dinv[node];
    sa1[wid][f]     = fmaxf(fmaf(dn, acc.x, b1[f]),     0.f);
    sa1[wid][f + 1] = fmaxf(fmaf(dn, acc.y, b1[f + 1]), 0.f);
    __syncwarp();                        // each warp reads only its own sa1 row
    const float2* sW2v = (const float2*)sW2t;
    float h0 = 0.f, h1v = 0.f;
    #pragma unroll 8
    for (int k = 0; k < HID; k++) {
        float a = sa1[wid][k];
        float2 w = sW2v[k * 32 + lane];
        h0  = fmaf(a, w.x, h0);
        h1v = fmaf(a, w.y, h1v);
    }
    ((float2*)g_a)[node * 32 + lane] = make_float2(dn * h0, dn * h1v);
}

// ---------------- agg2: pure-sum gather, clip [0,10], write comb ----------------
__global__ void k_agg2(const float* __restrict__ b2) {
    int tid = threadIdx.x, lane = tid & 31, wid = tid >> 5;
    int node = blockIdx.x * 8 + wid;
    if (node >= NN) return;
    float2 acc = gather_s((const float2*)g_a, node, lane);
    float dn = g_dinv[node];
    int f = lane * 2;
    float ox = fminf(fmaxf(fmaf(dn, acc.x, b2[f]),     0.f), 10.f);
    float oy = fminf(fmaxf(fmaf(dn, acc.y, b2[f + 1]), 0.f), 10.f);
    ((float2*)g_comb)[node * 32 + lane] = make_float2(ox, oy);
}

// ---------------- of1 matvec: race-free partials, no atomics ----------------
__global__ void k_of1(const float* __restrict__ W) {
    int r0 = blockIdx.y * RPB;
    const float4* __restrict__ v4 = (const float4*)g_comb;
    const float4* __restrict__ W4 = (const float4*)W;
    float acc[RPB];
    #pragma unroll
    for (int r = 0; r < RPB; r++) acc[r] = 0.f;
    int stride = gridDim.x * blockDim.x;
    for (int i = blockIdx.x * blockDim.x + threadIdx.x; i < COMB4; i += stride) {
        float4 c = v4[i];
        #pragma unroll
        for (int r = 0; r < RPB; r++) {
            float4 a = __ldcs(&W4[(size_t)(r0 + r) * COMB4 + i]);
            acc[r] = fmaf(a.x, c.x, acc[r]);
            acc[r] = fmaf(a.y, c.y, acc[r]);
            acc[r] = fmaf(a.z, c.z, acc[r]);
            acc[r] = fmaf(a.w, c.w, acc[r]);
        }
    }
    int lane = threadIdx.x & 31, wid = threadIdx.x >> 5;
    #pragma unroll
    for (int r = 0; r < RPB; r++) {
        #pragma unroll
        for (int o = 16; o > 0; o >>= 1)
            acc[r] += __shfl_down_sync(0xffffffffu, acc[r], o);
    }
    __shared__ float red[8][RPB];
    if (lane == 0) {
        #pragma unroll
        for (int r = 0; r < RPB; r++) red[wid][r] = acc[r];
    }
    __syncthreads();
    if (threadIdx.x < RPB) {
        float s = 0.f;
        #pragma unroll
        for (int w = 0; w < 8; w++) s += red[w][threadIdx.x];
        g_yp[blockIdx.x * 128 + r0 + threadIdx.x] = s;   // partial per chunk
    }
}

// ---------------- of2: reduce partials + final projection ----------------
__global__ void k_of2(const float* __restrict__ of1b, const float* __restrict__ of2W,
                      const float* __restrict__ of2b, float* __restrict__ out) {
    __shared__ float so[128];
    int tid = threadIdx.x;
    if (tid < 128) {
        float s = of1b[tid];
        #pragma unroll
        for (int c = 0; c < CH; c++) s += g_yp[c * 128 + tid];
        so[tid] = fmaxf(s, 0.f);
    }
    __syncthreads();
    int k = blockIdx.x * blockDim.x + tid;
    if (k < OUTD) {
        const float4* __restrict__ w4 = (const float4*)(of2W + (size_t)k * 128);
        float s = of2b[k];
        #pragma unroll
        for (int j = 0; j < 32; j++) {
            float4 a = __ldg(&w4[j]);
            s = fmaf(a.x, so[j * 4 + 0], s);
            s = fmaf(a.y, so[j * 4 + 1], s);
            s = fmaf(a.z, so[j * 4 + 2], s);
            s = fmaf(a.w, so[j * 4 + 3], s);
        }
        out[k] = s;
    }
}

// ---------------- host ----------------
extern "C" void kernel_launch(void* const* d_in, const int* in_sizes, int n_in,
                              void* d_out, int out_size) {
    const float* x     = (const float*)d_in[0];
    const int*   ei    = (const int*)d_in[1];
    const float* rain  = (const float*)d_in[2];
    const float* frain = (const float*)d_in[3];
    const float* W1    = (const float*)d_in[4];
    const float* b1    = (const float*)d_in[5];
    const float* W2    = (const float*)d_in[6];
    const float* b2    = (const float*)d_in[7];
    const float* wf1W  = (const float*)d_in[8];
    const float* wf1b  = (const float*)d_in[9];
    const float* wf2W  = (const float*)d_in[10];
    const float* wf2b  = (const float*)d_in[11];
    const float* of1W  = (const float*)d_in[12];
    const float* of1b  = (const float*)d_in[13];
    const float* of2W  = (const float*)d_in[14];
    const float* of2b  = (const float*)d_in[15];
    float* out = (float*)d_out;

    k_lin1z <<<353, 256>>>(x, W1);                 // h1 + zero heads
    k_fill  <<<(EE / 4 + 255) / 256, 256>>>(ei);   // buckets + degrees
    k_dinvW <<<41, 256>>>(rain, frain, wf1W, wf1b, wf2W, wf2b);
    k_aggLin<<<(NN + 31) / 32, 1024>>>(b1, W2);    // 32 warps, 1 node/warp
    k_agg2  <<<(NN + 7) / 8, 256>>>(b2);           // pure-sum gather -> comb
    k_of1   <<<dim3(CH, 8), 256>>>(of1W);          // partials, no atomics
    k_of2   <<<(OUTD + 255) / 256, 256>>>(of1b, of2W, of2b, out);
}